// round 9
// baseline (speedup 1.0000x reference)
#include <cuda_runtime.h>
#include <cstdint>

// MLP 64->4->8->8->32, sigmoid each layer, fp32, batch 1M (384MB traffic).
// Key model fix (R8 post-mortem): broadcast LDS.128 does NOT dedup (4 crossbar
// phases regardless), but warp-uniform LDG.128 coalesces to 1 sector (1 wf).
// => layers 1-2 weights + biases read straight from gmem via __ldg (L1-hit,
//    uniform), no smem staging. Removes ~half the L1 wavefronts per tile.
//  - select-free 3-shuffle reduce-scatter layer 0, conflict-free psum
//  - hidden sigmoid via tanh.approx.f32; output layer exp-based
//  - layer 3: f32x2 packed outputs, W3 interleaved in smem (lane-varying)
//  - warp-local dataflow, 8 blocks/SM

#define TPB 128
#define PK 34                 // psum k-stride (words)
#define PSUM_WARP (16 * PK)   // floats per warp region = 544
#define W3Q_STRIDE 44         // words per c4 group in sW3q (aligned, no-conflict)

__device__ __forceinline__ float sigmoidf_fast(float x) {   // output layer
    return __fdividef(1.0f, 1.0f + __expf(-x));
}
__device__ __forceinline__ float sigmoid_h(float x) {       // hidden layers
    float t;
    asm("tanh.approx.f32 %0, %1;" : "=f"(t) : "f"(0.5f * x));
    return fmaf(0.5f, t, 0.5f);
}

__device__ __forceinline__ float dot4(float4 a, float4 b) {
    float s = a.x * b.x;
    s = fmaf(a.y, b.y, s);
    s = fmaf(a.z, b.z, s);
    s = fmaf(a.w, b.w, s);
    return s;
}

__device__ __forceinline__ uint64_t pk2(float lo, float hi) {
    uint64_t r;
    asm("mov.b64 %0, {%1, %2};" : "=l"(r) : "f"(lo), "f"(hi));
    return r;
}
__device__ __forceinline__ void upk2(uint64_t v, float& lo, float& hi) {
    asm("mov.b64 {%0, %1}, %2;" : "=f"(lo), "=f"(hi) : "l"(v));
}
__device__ __forceinline__ uint64_t fma2(uint64_t a, uint64_t b, uint64_t c) {
    uint64_t d;
    asm("fma.rn.f32x2 %0, %1, %2, %3;" : "=l"(d) : "l"(a), "l"(b), "l"(c));
    return d;
}

__global__ void __launch_bounds__(TPB, 8)
mlp_kernel(const float* __restrict__ x,
           const float* __restrict__ W0, const float* __restrict__ b0,
           const float* __restrict__ W1, const float* __restrict__ b1,
           const float* __restrict__ W2, const float* __restrict__ b2,
           const float* __restrict__ W3, const float* __restrict__ b3,
           float* __restrict__ out, int batch)
{
    __shared__ __align__(16) float psum[4 * PSUM_WARP];   // 8704 B
    __shared__ __align__(16) float h2s[TPB * 12];         // 6144 B
    __shared__ __align__(16) float sW3q[8 * W3Q_STRIDE];  // interleaved W3

    const int tid  = threadIdx.x;
    const int lane = tid & 31;
    const int wid  = tid >> 5;

    // ---- W3 interleave into smem (lane-varying reads later) ----
    if (tid < 32) {
        // W3 output j, comp c -> sW3q[(j>>2)*44 + c*4 + (j&3)]
        #pragma unroll
        for (int cc = 0; cc < 8; ++cc)
            sW3q[(tid >> 2) * W3Q_STRIDE + cc * 4 + (tid & 3)] = W3[tid * 8 + cc];
    }
    __syncthreads();

    const int warpRow = (blockIdx.x * (TPB / 32) + wid) * 32;
    if (warpRow >= batch) return;          // whole-warp exit only

    if (warpRow + 32 <= batch) {
        // ===================== fast path: full warp =====================
        // W0 fragment in regs, rows PERMUTED per lane -> select-free butterfly
        const int c   = lane & 15;
        const int b0i = lane & 1;
        const int b1i = (lane >> 1) & 1;
        const float4 w0f0 = __ldg((const float4*)(W0 + (2*b1i +  b0i     ) * 64) + c);
        const float4 w0f1 = __ldg((const float4*)(W0 + (2*b1i + (b0i ^ 1)) * 64) + c);
        const float4 w0f2 = __ldg((const float4*)(W0 + (2*(b1i^1) +  b0i     ) * 64) + c);
        const float4 w0f3 = __ldg((const float4*)(W0 + (2*(b1i^1) + (b0i ^ 1)) * 64) + c);

        const float4* __restrict__ xw = (const float4*)x + (size_t)warpRow * 16;
        const int pw = wid * PSUM_WARP;
        // store slot: [k = lane&15][row = 2i + (lane>>4)], bank = 2k+row
        const int sbase = pw + (lane & 15) * PK + (lane >> 4);

        // ---- layer 0: 4 dots + 3 shuffles + 1 STS per iter, no selects ----
        #pragma unroll
        for (int i = 0; i < 16; ++i) {
            float4 v = __ldcs(&xw[i * 32 + lane]);   // coalesced LDG.128
            float p0 = dot4(v, w0f0);
            float p1 = dot4(v, w0f1);
            float p2 = dot4(v, w0f2);
            float p3 = dot4(v, w0f3);
            float u0 = p0 + __shfl_xor_sync(0xffffffffu, p1, 1);
            float u1 = p2 + __shfl_xor_sync(0xffffffffu, p3, 1);
            float r4 = u0 + __shfl_xor_sync(0xffffffffu, u1, 2);
            psum[sbase + 2 * i] = r4;                // conflict-free STS
        }
        __syncwarp();

        // ---- per-row: finish layer 0 (16 scalar LDS, conflict-free) ----
        float vk[16];
        #pragma unroll
        for (int k = 0; k < 16; ++k) vk[k] = psum[pw + k * PK + lane];
        const float4 b0v = __ldg((const float4*)b0);         // uniform, 1 wf
        float4 h0;
        h0.x = sigmoid_h(((vk[0] + vk[4]) + (vk[8]  + vk[12])) + b0v.x);
        h0.y = sigmoid_h(((vk[1] + vk[5]) + (vk[9]  + vk[13])) + b0v.y);
        h0.z = sigmoid_h(((vk[2] + vk[6]) + (vk[10] + vk[14])) + b0v.z);
        h0.w = sigmoid_h(((vk[3] + vk[7]) + (vk[11] + vk[15])) + b0v.w);

        // ---- layer 1: 4 -> 8 (uniform gmem weights: 1 wf per load) ----
        const float4 b1v0 = __ldg((const float4*)b1);
        const float4 b1v1 = __ldg((const float4*)b1 + 1);
        const float b1s[8] = {b1v0.x, b1v0.y, b1v0.z, b1v0.w,
                              b1v1.x, b1v1.y, b1v1.z, b1v1.w};
        float h1[8];
        #pragma unroll
        for (int j = 0; j < 8; ++j) {
            float4 w = __ldg((const float4*)W1 + j);
            h1[j] = sigmoid_h(b1s[j] + dot4(h0, w));
        }
        float4 ha = make_float4(h1[0], h1[1], h1[2], h1[3]);
        float4 hb = make_float4(h1[4], h1[5], h1[6], h1[7]);

        // ---- layer 2: 8 -> 8 (uniform gmem weights) ----
        const float4 b2v0 = __ldg((const float4*)b2);
        const float4 b2v1 = __ldg((const float4*)b2 + 1);
        const float b2s[8] = {b2v0.x, b2v0.y, b2v0.z, b2v0.w,
                              b2v1.x, b2v1.y, b2v1.z, b2v1.w};
        float h2[8];
        #pragma unroll
        for (int j = 0; j < 8; ++j) {
            float4 wa = __ldg((const float4*)W2 + j * 2);
            float4 wb = __ldg((const float4*)W2 + j * 2 + 1);
            h2[j] = sigmoid_h(b2s[j] + dot4(ha, wa) + dot4(hb, wb));
        }

        *(float4*)&h2s[tid * 12]     = make_float4(h2[0], h2[1], h2[2], h2[3]);
        *(float4*)&h2s[tid * 12 + 4] = make_float4(h2[4], h2[5], h2[6], h2[7]);
        __syncwarp();

        // ---- layer 3: packed-output f32x2; interleaved W3 from smem ----
        const int c4 = lane & 7;
        uint64_t wq01[8], wq23[8];
        #pragma unroll
        for (int cc = 0; cc < 8; ++cc) {
            float4 w = *(const float4*)&sW3q[c4 * W3Q_STRIDE + cc * 4];
            wq01[cc] = pk2(w.x, w.y);
            wq23[cc] = pk2(w.z, w.w);
        }
        const float4 b3v = __ldg((const float4*)b3 + c4);
        const uint64_t bp01 = pk2(b3v.x, b3v.y);
        const uint64_t bp23 = pk2(b3v.z, b3v.w);

        float4* __restrict__ ow = (float4*)out + (size_t)warpRow * 8;
        const int prow = wid * 32;
        #pragma unroll
        for (int k = 0; k < 8; ++k) {
            int gi = k * 32 + lane;
            int rl = prow + (gi >> 3);               // local row owning gi
            float4 ra = *(const float4*)&h2s[rl * 12];
            float4 rb = *(const float4*)&h2s[rl * 12 + 4];
            uint64_t a01 = bp01, a23 = bp23;
            uint64_t hd;
            hd = pk2(ra.x, ra.x); a01 = fma2(hd, wq01[0], a01); a23 = fma2(hd, wq23[0], a23);
            hd = pk2(ra.y, ra.y); a01 = fma2(hd, wq01[1], a01); a23 = fma2(hd, wq23[1], a23);
            hd = pk2(ra.z, ra.z); a01 = fma2(hd, wq01[2], a01); a23 = fma2(hd, wq23[2], a23);
            hd = pk2(ra.w, ra.w); a01 = fma2(hd, wq01[3], a01); a23 = fma2(hd, wq23[3], a23);
            hd = pk2(rb.x, rb.x); a01 = fma2(hd, wq01[4], a01); a23 = fma2(hd, wq23[4], a23);
            hd = pk2(rb.y, rb.y); a01 = fma2(hd, wq01[5], a01); a23 = fma2(hd, wq23[5], a23);
            hd = pk2(rb.z, rb.z); a01 = fma2(hd, wq01[6], a01); a23 = fma2(hd, wq23[6], a23);
            hd = pk2(rb.w, rb.w); a01 = fma2(hd, wq01[7], a01); a23 = fma2(hd, wq23[7], a23);
            float s0, s1, s2, s3;
            upk2(a01, s0, s1);
            upk2(a23, s2, s3);
            __stcs(&ow[gi], make_float4(sigmoidf_fast(s0), sigmoidf_fast(s1),
                                        sigmoidf_fast(s2), sigmoidf_fast(s3)));
        }
    } else {
        // ============== tail path: per-row scalar (rare) ==============
        const int row = warpRow + lane;
        if (row < batch) {
            const float* xr = x + (size_t)row * 64;
            float t0[4];
            #pragma unroll
            for (int j = 0; j < 4; ++j) {
                float s = b0[j];
                for (int k = 0; k < 64; ++k) s = fmaf(xr[k], W0[j * 64 + k], s);
                t0[j] = sigmoid_h(s);
            }
            float t1[8];
            #pragma unroll
            for (int j = 0; j < 8; ++j) {
                float s = b1[j];
                for (int k = 0; k < 4; ++k) s = fmaf(t0[k], W1[j * 4 + k], s);
                t1[j] = sigmoid_h(s);
            }
            float t2[8];
            #pragma unroll
            for (int j = 0; j < 8; ++j) {
                float s = b2[j];
                for (int k = 0; k < 8; ++k) s = fmaf(t1[k], W2[j * 8 + k], s);
                t2[j] = sigmoid_h(s);
            }
            float* orow = out + (size_t)row * 32;
            #pragma unroll
            for (int j = 0; j < 32; ++j) {
                float s = b3[j];
                for (int k = 0; k < 8; ++k) s = fmaf(t2[k], W3[j * 8 + k], s);
                orow[j] = sigmoidf_fast(s);
            }
        }
    }
}

extern "C" void kernel_launch(void* const* d_in, const int* in_sizes, int n_in,
                              void* d_out, int out_size)
{
    const float* x  = (const float*)d_in[0];
    const float* W0 = (const float*)d_in[1];
    const float* b0 = (const float*)d_in[2];
    const float* W1 = (const float*)d_in[3];
    const float* b1 = (const float*)d_in[4];
    const float* W2 = (const float*)d_in[5];
    const float* b2 = (const float*)d_in[6];
    const float* W3 = (const float*)d_in[7];
    const float* b3 = (const float*)d_in[8];
    float* out = (float*)d_out;

    int batch = in_sizes[0] / 64;
    int grid = (batch + TPB - 1) / TPB;
    mlp_kernel<<<grid, TPB>>>(x, W0, b0, W1, b1, W2, b2, W3, b3, out, batch);
}

// round 11
// speedup vs baseline: 1.0560x; 1.0560x over previous
#include <cuda_runtime.h>
#include <cstdint>

// MLP 64->4->8->8->32, sigmoid each layer, fp32, batch 1M (384MB traffic).
// R9 lesson: uniform LDG shares the LSU/L1 pipe with LDS -> no relief.
// R10/R11: W1/W2/biases in the CONSTANT BANK (uniform port, ULDC, zero L1
// crossbar phases). Filled per-launch via pack-kernel + one D2D memcpy into
// the __constant__ symbol (both graph-capturable, no allocations).
//  - select-free 3-shuffle reduce-scatter layer 0, conflict-free psum
//  - hidden sigmoid tanh.approx; output sigmoid exp-based
//  - layer 3: f32x2 packed outputs, W3 interleaved in smem (lane-varying)
//  - warp-local dataflow, 8 blocks/SM (64-reg cap)

#define TPB 128
#define PK 34                 // psum k-stride (words)
#define PSUM_WARP (16 * PK)   // floats per warp region = 544
#define W3Q_STRIDE 44         // words per c4 group in sW3q (aligned, no-conflict)

// constant-bank weight block: [0:32) W1, [32:96) W2, [96:104) b1,
// [104:112) b2, [112:116) b0
__constant__ __align__(16) float cw[116];
__device__   __align__(16) float gstage[116];

__device__ __forceinline__ float sigmoidf_fast(float x) {   // output layer
    return __fdividef(1.0f, 1.0f + __expf(-x));
}
__device__ __forceinline__ float sigmoid_h(float x) {       // hidden layers
    float t;
    asm("tanh.approx.f32 %0, %1;" : "=f"(t) : "f"(0.5f * x));
    return fmaf(0.5f, t, 0.5f);
}

__device__ __forceinline__ float dot4(float4 a, float4 b) {
    float s = a.x * b.x;
    s = fmaf(a.y, b.y, s);
    s = fmaf(a.z, b.z, s);
    s = fmaf(a.w, b.w, s);
    return s;
}

__device__ __forceinline__ uint64_t pk2(float lo, float hi) {
    uint64_t r;
    asm("mov.b64 %0, {%1, %2};" : "=l"(r) : "f"(lo), "f"(hi));
    return r;
}
__device__ __forceinline__ void upk2(uint64_t v, float& lo, float& hi) {
    asm("mov.b64 {%0, %1}, %2;" : "=f"(lo), "=f"(hi) : "l"(v));
}
__device__ __forceinline__ uint64_t fma2(uint64_t a, uint64_t b, uint64_t c) {
    uint64_t d;
    asm("fma.rn.f32x2 %0, %1, %2, %3;" : "=l"(d) : "l"(a), "l"(b), "l"(c));
    return d;
}

__global__ void pack_kernel(const float* __restrict__ W1, const float* __restrict__ b1,
                            const float* __restrict__ W2, const float* __restrict__ b2,
                            const float* __restrict__ b0)
{
    int t = threadIdx.x;
    if (t < 32)        gstage[t] = W1[t];
    else if (t < 96)   gstage[t] = W2[t - 32];
    else if (t < 104)  gstage[t] = b1[t - 96];
    else if (t < 112)  gstage[t] = b2[t - 104];
    else if (t < 116)  gstage[t] = b0[t - 112];
}

__global__ void __launch_bounds__(TPB, 8)
mlp_kernel(const float* __restrict__ x,
           const float* __restrict__ W0,
           const float* __restrict__ W3, const float* __restrict__ b3,
           float* __restrict__ out, int batch)
{
    __shared__ __align__(16) float psum[4 * PSUM_WARP];   // 8704 B
    __shared__ __align__(16) float h2s[TPB * 12];         // 6144 B
    __shared__ __align__(16) float sW3q[8 * W3Q_STRIDE];  // interleaved W3

    const int tid  = threadIdx.x;
    const int lane = tid & 31;
    const int wid  = tid >> 5;

    // ---- W3 interleave into smem (lane-varying reads later) ----
    if (tid < 32) {
        // W3 output j, comp c -> sW3q[(j>>2)*44 + c*4 + (j&3)]
        #pragma unroll
        for (int cc = 0; cc < 8; ++cc)
            sW3q[(tid >> 2) * W3Q_STRIDE + cc * 4 + (tid & 3)] = W3[tid * 8 + cc];
    }
    __syncthreads();

    const int warpRow = (blockIdx.x * (TPB / 32) + wid) * 32;
    if (warpRow >= batch) return;          // whole-warp exit only

    if (warpRow + 32 <= batch) {
        // ===================== fast path: full warp =====================
        // W0 fragment in regs, rows PERMUTED per lane -> select-free butterfly
        const int c   = lane & 15;
        const int b0i = lane & 1;
        const int b1i = (lane >> 1) & 1;
        const float4 w0f0 = __ldg((const float4*)(W0 + (2*b1i +  b0i     ) * 64) + c);
        const float4 w0f1 = __ldg((const float4*)(W0 + (2*b1i + (b0i ^ 1)) * 64) + c);
        const float4 w0f2 = __ldg((const float4*)(W0 + (2*(b1i^1) +  b0i     ) * 64) + c);
        const float4 w0f3 = __ldg((const float4*)(W0 + (2*(b1i^1) + (b0i ^ 1)) * 64) + c);

        const float4* __restrict__ xw = (const float4*)x + (size_t)warpRow * 16;
        const int pw = wid * PSUM_WARP;
        // store slot: [k = lane&15][row = 2i + (lane>>4)], bank = 2k+row
        const int sbase = pw + (lane & 15) * PK + (lane >> 4);

        // ---- layer 0: 4 dots + 3 shuffles + 1 STS per iter, no selects ----
        #pragma unroll
        for (int i = 0; i < 16; ++i) {
            float4 v = __ldcs(&xw[i * 32 + lane]);   // coalesced LDG.128
            float p0 = dot4(v, w0f0);
            float p1 = dot4(v, w0f1);
            float p2 = dot4(v, w0f2);
            float p3 = dot4(v, w0f3);
            float u0 = p0 + __shfl_xor_sync(0xffffffffu, p1, 1);
            float u1 = p2 + __shfl_xor_sync(0xffffffffu, p3, 1);
            float r4 = u0 + __shfl_xor_sync(0xffffffffu, u1, 2);
            psum[sbase + 2 * i] = r4;                // conflict-free STS
        }
        __syncwarp();

        // ---- per-row: finish layer 0 (16 scalar LDS, conflict-free) ----
        float vk[16];
        #pragma unroll
        for (int k = 0; k < 16; ++k) vk[k] = psum[pw + k * PK + lane];
        float4 h0;
        h0.x = sigmoid_h(((vk[0] + vk[4]) + (vk[8]  + vk[12])) + cw[112]);
        h0.y = sigmoid_h(((vk[1] + vk[5]) + (vk[9]  + vk[13])) + cw[113]);
        h0.z = sigmoid_h(((vk[2] + vk[6]) + (vk[10] + vk[14])) + cw[114]);
        h0.w = sigmoid_h(((vk[3] + vk[7]) + (vk[11] + vk[15])) + cw[115]);

        // ---- layer 1: 4 -> 8 (constant bank: uniform port, off L1) ----
        float h1[8];
        #pragma unroll
        for (int j = 0; j < 8; ++j) {
            float4 w = *(const float4*)&cw[j * 4];
            h1[j] = sigmoid_h(cw[96 + j] + dot4(h0, w));
        }
        float4 ha = make_float4(h1[0], h1[1], h1[2], h1[3]);
        float4 hb = make_float4(h1[4], h1[5], h1[6], h1[7]);

        // ---- layer 2: 8 -> 8 (constant bank) ----
        float h2[8];
        #pragma unroll
        for (int j = 0; j < 8; ++j) {
            float4 wa = *(const float4*)&cw[32 + j * 8];
            float4 wb = *(const float4*)&cw[32 + j * 8 + 4];
            h2[j] = sigmoid_h(cw[104 + j] + dot4(ha, wa) + dot4(hb, wb));
        }

        *(float4*)&h2s[tid * 12]     = make_float4(h2[0], h2[1], h2[2], h2[3]);
        *(float4*)&h2s[tid * 12 + 4] = make_float4(h2[4], h2[5], h2[6], h2[7]);
        __syncwarp();

        // ---- layer 3: packed-output f32x2; interleaved W3 from smem ----
        const int c4 = lane & 7;
        uint64_t wq01[8], wq23[8];
        #pragma unroll
        for (int cc = 0; cc < 8; ++cc) {
            float4 w = *(const float4*)&sW3q[c4 * W3Q_STRIDE + cc * 4];
            wq01[cc] = pk2(w.x, w.y);
            wq23[cc] = pk2(w.z, w.w);
        }
        const float4 b3v = __ldg((const float4*)b3 + c4);
        const uint64_t bp01 = pk2(b3v.x, b3v.y);
        const uint64_t bp23 = pk2(b3v.z, b3v.w);

        float4* __restrict__ ow = (float4*)out + (size_t)warpRow * 8;
        const int prow = wid * 32;
        #pragma unroll
        for (int k = 0; k < 8; ++k) {
            int gi = k * 32 + lane;
            int rl = prow + (gi >> 3);               // local row owning gi
            float4 ra = *(const float4*)&h2s[rl * 12];
            float4 rb = *(const float4*)&h2s[rl * 12 + 4];
            uint64_t a01 = bp01, a23 = bp23;
            uint64_t hd;
            hd = pk2(ra.x, ra.x); a01 = fma2(hd, wq01[0], a01); a23 = fma2(hd, wq23[0], a23);
            hd = pk2(ra.y, ra.y); a01 = fma2(hd, wq01[1], a01); a23 = fma2(hd, wq23[1], a23);
            hd = pk2(ra.z, ra.z); a01 = fma2(hd, wq01[2], a01); a23 = fma2(hd, wq23[2], a23);
            hd = pk2(ra.w, ra.w); a01 = fma2(hd, wq01[3], a01); a23 = fma2(hd, wq23[3], a23);
            hd = pk2(rb.x, rb.x); a01 = fma2(hd, wq01[4], a01); a23 = fma2(hd, wq23[4], a23);
            hd = pk2(rb.y, rb.y); a01 = fma2(hd, wq01[5], a01); a23 = fma2(hd, wq23[5], a23);
            hd = pk2(rb.z, rb.z); a01 = fma2(hd, wq01[6], a01); a23 = fma2(hd, wq23[6], a23);
            hd = pk2(rb.w, rb.w); a01 = fma2(hd, wq01[7], a01); a23 = fma2(hd, wq23[7], a23);
            float s0, s1, s2, s3;
            upk2(a01, s0, s1);
            upk2(a23, s2, s3);
            __stcs(&ow[gi], make_float4(sigmoidf_fast(s0), sigmoidf_fast(s1),
                                        sigmoidf_fast(s2), sigmoidf_fast(s3)));
        }
    } else {
        // ============== tail path: per-row scalar (rare) ==============
        const int row = warpRow + lane;
        if (row < batch) {
            const float* xr = x + (size_t)row * 64;
            float t0[4];
            #pragma unroll
            for (int j = 0; j < 4; ++j) {
                float s = cw[112 + j];
                for (int k = 0; k < 64; ++k) s = fmaf(xr[k], W0[j * 64 + k], s);
                t0[j] = sigmoid_h(s);
            }
            float t1[8];
            #pragma unroll
            for (int j = 0; j < 8; ++j) {
                float s = cw[96 + j];
                for (int k = 0; k < 4; ++k) s = fmaf(t0[k], cw[j * 4 + k], s);
                t1[j] = sigmoid_h(s);
            }
            float t2[8];
            #pragma unroll
            for (int j = 0; j < 8; ++j) {
                float s = cw[104 + j];
                for (int k = 0; k < 8; ++k) s = fmaf(t1[k], cw[32 + j * 8 + k], s);
                t2[j] = sigmoid_h(s);
            }
            float* orow = out + (size_t)row * 32;
            #pragma unroll
            for (int j = 0; j < 32; ++j) {
                float s = b3[j];
                for (int k = 0; k < 8; ++k) s = fmaf(t2[k], W3[j * 8 + k], s);
                orow[j] = sigmoidf_fast(s);
            }
        }
    }
}

extern "C" void kernel_launch(void* const* d_in, const int* in_sizes, int n_in,
                              void* d_out, int out_size)
{
    const float* x  = (const float*)d_in[0];
    const float* W0 = (const float*)d_in[1];
    const float* b0 = (const float*)d_in[2];
    const float* W1 = (const float*)d_in[3];
    const float* b1 = (const float*)d_in[4];
    const float* W2 = (const float*)d_in[5];
    const float* b2 = (const float*)d_in[6];
    const float* W3 = (const float*)d_in[7];
    const float* b3 = (const float*)d_in[8];
    float* out = (float*)d_out;

    int batch = in_sizes[0] / 64;
    int grid = (batch + TPB - 1) / TPB;

    // 1) gather small weights into contiguous device staging
    pack_kernel<<<1, 128>>>(W1, b1, W2, b2, b0);
    // 2) D2D copy into the constant bank (graph-capturable memcpy node)
    void* gstage_ptr = nullptr;
    cudaGetSymbolAddress(&gstage_ptr, gstage);
    cudaMemcpyToSymbolAsync(cw, gstage_ptr, 116 * sizeof(float), 0,
                            cudaMemcpyDeviceToDevice, 0);
    // 3) main kernel reads cw via the uniform/constant port
    mlp_kernel<<<grid, TPB>>>(x, W0, W3, b3, out, batch);
}

// round 12
// speedup vs baseline: 1.0565x; 1.0005x over previous
#include <cuda_runtime.h>
#include <cstdint>

// MLP 64->4->8->8->32, sigmoid each layer, fp32, batch 1M (384MB traffic).
// R11 frame (constant-bank W1/W2/biases, select-free butterfly, psum
// exchange, f32x2 layer 3, W3 smem interleave, occ-8) plus:
//  - ALL sigmoids via tanh.approx (evidence R8: HW error ~1e-7 here)
//  - the tanh x/2 pre-scale folded into weights: constant bank holds
//    0.5*W1/W2/biases, W0 fragment halved once in regs, W3 halved at
//    interleave, b3 halved after load -> zero per-activation scale FMULs.

#define TPB 128
#define PK 34                 // psum k-stride (words)
#define PSUM_WARP (16 * PK)   // floats per warp region = 544
#define W3Q_STRIDE 44         // words per c4 group in sW3q (aligned, no-conflict)

// constant bank (all values PRE-HALVED): [0:32) W1/2, [32:96) W2/2,
// [96:104) b1/2, [104:112) b2/2, [112:116) b0/2
__constant__ __align__(16) float cw[116];
__device__   __align__(16) float gstage[116];

// x must already be halved: sigma(2s) = 0.5*tanh(s) + 0.5
__device__ __forceinline__ float sigmoid_half(float s) {
    float t;
    asm("tanh.approx.f32 %0, %1;" : "=f"(t) : "f"(s));
    return fmaf(0.5f, t, 0.5f);
}

__device__ __forceinline__ float dot4(float4 a, float4 b) {
    float s = a.x * b.x;
    s = fmaf(a.y, b.y, s);
    s = fmaf(a.z, b.z, s);
    s = fmaf(a.w, b.w, s);
    return s;
}

__device__ __forceinline__ uint64_t pk2(float lo, float hi) {
    uint64_t r;
    asm("mov.b64 %0, {%1, %2};" : "=l"(r) : "f"(lo), "f"(hi));
    return r;
}
__device__ __forceinline__ void upk2(uint64_t v, float& lo, float& hi) {
    asm("mov.b64 {%0, %1}, %2;" : "=f"(lo), "=f"(hi) : "l"(v));
}
__device__ __forceinline__ uint64_t fma2(uint64_t a, uint64_t b, uint64_t c) {
    uint64_t d;
    asm("fma.rn.f32x2 %0, %1, %2, %3;" : "=l"(d) : "l"(a), "l"(b), "l"(c));
    return d;
}

__global__ void pack_kernel(const float* __restrict__ W1, const float* __restrict__ b1,
                            const float* __restrict__ W2, const float* __restrict__ b2,
                            const float* __restrict__ b0)
{
    int t = threadIdx.x;
    if (t < 32)        gstage[t] = 0.5f * W1[t];
    else if (t < 96)   gstage[t] = 0.5f * W2[t - 32];
    else if (t < 104)  gstage[t] = 0.5f * b1[t - 96];
    else if (t < 112)  gstage[t] = 0.5f * b2[t - 104];
    else if (t < 116)  gstage[t] = 0.5f * b0[t - 112];
}

__global__ void __launch_bounds__(TPB, 8)
mlp_kernel(const float* __restrict__ x,
           const float* __restrict__ W0,
           const float* __restrict__ W3, const float* __restrict__ b3,
           float* __restrict__ out, int batch)
{
    __shared__ __align__(16) float psum[4 * PSUM_WARP];   // 8704 B
    __shared__ __align__(16) float h2s[TPB * 12];         // 6144 B
    __shared__ __align__(16) float sW3q[8 * W3Q_STRIDE];  // interleaved 0.5*W3

    const int tid  = threadIdx.x;
    const int lane = tid & 31;
    const int wid  = tid >> 5;

    // ---- 0.5*W3 interleave into smem (lane-varying reads later) ----
    if (tid < 32) {
        // W3 output j, comp c -> sW3q[(j>>2)*44 + c*4 + (j&3)]
        #pragma unroll
        for (int cc = 0; cc < 8; ++cc)
            sW3q[(tid >> 2) * W3Q_STRIDE + cc * 4 + (tid & 3)] = 0.5f * W3[tid * 8 + cc];
    }
    __syncthreads();

    const int warpRow = (blockIdx.x * (TPB / 32) + wid) * 32;
    if (warpRow >= batch) return;          // whole-warp exit only

    if (warpRow + 32 <= batch) {
        // ===================== fast path: full warp =====================
        // 0.5*W0 fragment in regs, rows PERMUTED -> select-free butterfly
        const int c   = lane & 15;
        const int b0i = lane & 1;
        const int b1i = (lane >> 1) & 1;
        float4 w0f0 = __ldg((const float4*)(W0 + (2*b1i +  b0i     ) * 64) + c);
        float4 w0f1 = __ldg((const float4*)(W0 + (2*b1i + (b0i ^ 1)) * 64) + c);
        float4 w0f2 = __ldg((const float4*)(W0 + (2*(b1i^1) +  b0i     ) * 64) + c);
        float4 w0f3 = __ldg((const float4*)(W0 + (2*(b1i^1) + (b0i ^ 1)) * 64) + c);
        w0f0.x *= 0.5f; w0f0.y *= 0.5f; w0f0.z *= 0.5f; w0f0.w *= 0.5f;
        w0f1.x *= 0.5f; w0f1.y *= 0.5f; w0f1.z *= 0.5f; w0f1.w *= 0.5f;
        w0f2.x *= 0.5f; w0f2.y *= 0.5f; w0f2.z *= 0.5f; w0f2.w *= 0.5f;
        w0f3.x *= 0.5f; w0f3.y *= 0.5f; w0f3.z *= 0.5f; w0f3.w *= 0.5f;

        const float4* __restrict__ xw = (const float4*)x + (size_t)warpRow * 16;
        const int pw = wid * PSUM_WARP;
        // store slot: [k = lane&15][row = 2i + (lane>>4)], bank = 2k+row
        const int sbase = pw + (lane & 15) * PK + (lane >> 4);

        // ---- layer 0: 4 dots + 3 shuffles + 1 STS per iter, no selects ----
        #pragma unroll
        for (int i = 0; i < 16; ++i) {
            float4 v = __ldcs(&xw[i * 32 + lane]);   // coalesced LDG.128
            float p0 = dot4(v, w0f0);
            float p1 = dot4(v, w0f1);
            float p2 = dot4(v, w0f2);
            float p3 = dot4(v, w0f3);
            float u0 = p0 + __shfl_xor_sync(0xffffffffu, p1, 1);
            float u1 = p2 + __shfl_xor_sync(0xffffffffu, p3, 1);
            float r4 = u0 + __shfl_xor_sync(0xffffffffu, u1, 2);
            psum[sbase + 2 * i] = r4;                // conflict-free STS
        }
        __syncwarp();

        // ---- per-row: finish layer 0 (16 scalar LDS, conflict-free) ----
        float vk[16];
        #pragma unroll
        for (int k = 0; k < 16; ++k) vk[k] = psum[pw + k * PK + lane];
        float4 h0;   // sums are pre-halved; cw[112..] is 0.5*b0
        h0.x = sigmoid_half(((vk[0] + vk[4]) + (vk[8]  + vk[12])) + cw[112]);
        h0.y = sigmoid_half(((vk[1] + vk[5]) + (vk[9]  + vk[13])) + cw[113]);
        h0.z = sigmoid_half(((vk[2] + vk[6]) + (vk[10] + vk[14])) + cw[114]);
        h0.w = sigmoid_half(((vk[3] + vk[7]) + (vk[11] + vk[15])) + cw[115]);

        // ---- layer 1: 4 -> 8 (constant bank, pre-halved) ----
        float h1[8];
        #pragma unroll
        for (int j = 0; j < 8; ++j) {
            float4 w = *(const float4*)&cw[j * 4];
            h1[j] = sigmoid_half(cw[96 + j] + dot4(h0, w));
        }
        float4 ha = make_float4(h1[0], h1[1], h1[2], h1[3]);
        float4 hb = make_float4(h1[4], h1[5], h1[6], h1[7]);

        // ---- layer 2: 8 -> 8 (constant bank, pre-halved) ----
        float h2[8];
        #pragma unroll
        for (int j = 0; j < 8; ++j) {
            float4 wa = *(const float4*)&cw[32 + j * 8];
            float4 wb = *(const float4*)&cw[32 + j * 8 + 4];
            h2[j] = sigmoid_half(cw[104 + j] + dot4(ha, wa) + dot4(hb, wb));
        }

        *(float4*)&h2s[tid * 12]     = make_float4(h2[0], h2[1], h2[2], h2[3]);
        *(float4*)&h2s[tid * 12 + 4] = make_float4(h2[4], h2[5], h2[6], h2[7]);
        __syncwarp();

        // ---- layer 3: packed f32x2, pre-halved weights/bias ----
        const int c4 = lane & 7;
        uint64_t wq01[8], wq23[8];
        #pragma unroll
        for (int cc = 0; cc < 8; ++cc) {
            float4 w = *(const float4*)&sW3q[c4 * W3Q_STRIDE + cc * 4];
            wq01[cc] = pk2(w.x, w.y);
            wq23[cc] = pk2(w.z, w.w);
        }
        const float4 b3v = __ldg((const float4*)b3 + c4);
        const uint64_t bp01 = pk2(0.5f * b3v.x, 0.5f * b3v.y);
        const uint64_t bp23 = pk2(0.5f * b3v.z, 0.5f * b3v.w);

        float4* __restrict__ ow = (float4*)out + (size_t)warpRow * 8;
        const int prow = wid * 32;
        #pragma unroll
        for (int k = 0; k < 8; ++k) {
            int gi = k * 32 + lane;
            int rl = prow + (gi >> 3);               // local row owning gi
            float4 ra = *(const float4*)&h2s[rl * 12];
            float4 rb = *(const float4*)&h2s[rl * 12 + 4];
            uint64_t a01 = bp01, a23 = bp23;
            uint64_t hd;
            hd = pk2(ra.x, ra.x); a01 = fma2(hd, wq01[0], a01); a23 = fma2(hd, wq23[0], a23);
            hd = pk2(ra.y, ra.y); a01 = fma2(hd, wq01[1], a01); a23 = fma2(hd, wq23[1], a23);
            hd = pk2(ra.z, ra.z); a01 = fma2(hd, wq01[2], a01); a23 = fma2(hd, wq23[2], a23);
            hd = pk2(ra.w, ra.w); a01 = fma2(hd, wq01[3], a01); a23 = fma2(hd, wq23[3], a23);
            hd = pk2(rb.x, rb.x); a01 = fma2(hd, wq01[4], a01); a23 = fma2(hd, wq23[4], a23);
            hd = pk2(rb.y, rb.y); a01 = fma2(hd, wq01[5], a01); a23 = fma2(hd, wq23[5], a23);
            hd = pk2(rb.z, rb.z); a01 = fma2(hd, wq01[6], a01); a23 = fma2(hd, wq23[6], a23);
            hd = pk2(rb.w, rb.w); a01 = fma2(hd, wq01[7], a01); a23 = fma2(hd, wq23[7], a23);
            float s0, s1, s2, s3;
            upk2(a01, s0, s1);
            upk2(a23, s2, s3);
            __stcs(&ow[gi], make_float4(sigmoid_half(s0), sigmoid_half(s1),
                                        sigmoid_half(s2), sigmoid_half(s3)));
        }
    } else {
        // ====== tail path (cold; none at batch=1M): cw is PRE-HALVED ======
        const int row = warpRow + lane;
        if (row < batch) {
            const float* xr = x + (size_t)row * 64;
            float t0[4];
            #pragma unroll
            for (int j = 0; j < 4; ++j) {
                float s = cw[112 + j];                       // 0.5*b0
                for (int k = 0; k < 64; ++k)
                    s = fmaf(0.5f * xr[k], W0[j * 64 + k], s);
                t0[j] = sigmoid_half(s);
            }
            float t1[8];
            #pragma unroll
            for (int j = 0; j < 8; ++j) {
                float s = cw[96 + j];                        // 0.5*b1
                for (int k = 0; k < 4; ++k) s = fmaf(t0[k], cw[j * 4 + k], s);
                t1[j] = sigmoid_half(s);
            }
            float t2[8];
            #pragma unroll
            for (int j = 0; j < 8; ++j) {
                float s = cw[104 + j];                       // 0.5*b2
                for (int k = 0; k < 8; ++k) s = fmaf(t1[k], cw[32 + j * 8 + k], s);
                t2[j] = sigmoid_half(s);
            }
            float* orow = out + (size_t)row * 32;
            #pragma unroll
            for (int j = 0; j < 32; ++j) {
                float s = 0.5f * b3[j];
                for (int k = 0; k < 8; ++k)
                    s = fmaf(t2[k], 0.5f * W3[j * 8 + k], s);
                orow[j] = sigmoid_half(s);
            }
        }
    }
}

extern "C" void kernel_launch(void* const* d_in, const int* in_sizes, int n_in,
                              void* d_out, int out_size)
{
    const float* x  = (const float*)d_in[0];
    const float* W0 = (const float*)d_in[1];
    const float* b0 = (const float*)d_in[2];
    const float* W1 = (const float*)d_in[3];
    const float* b1 = (const float*)d_in[4];
    const float* W2 = (const float*)d_in[5];
    const float* b2 = (const float*)d_in[6];
    const float* W3 = (const float*)d_in[7];
    const float* b3 = (const float*)d_in[8];
    float* out = (float*)d_out;

    int batch = in_sizes[0] / 64;
    int grid = (batch + TPB - 1) / TPB;

    // 1) gather + pre-halve small weights into device staging
    pack_kernel<<<1, 128>>>(W1, b1, W2, b2, b0);
    // 2) D2D copy into the constant bank (graph-capturable memcpy node)
    void* gstage_ptr = nullptr;
    cudaGetSymbolAddress(&gstage_ptr, gstage);
    cudaMemcpyToSymbolAsync(cw, gstage_ptr, 116 * sizeof(float), 0,
                            cudaMemcpyDeviceToDevice, 0);
    // 3) main kernel
    mlp_kernel<<<grid, TPB>>>(x, W0, W3, b3, out, batch);
}